// round 1
// baseline (speedup 1.0000x reference)
#include <cuda_runtime.h>

// Problem: S=8, N=2048, D=256
//   qt0[s,j,d] = sum_e kernel[d,e] * tensor0[s,j,e]          (GEMM-NT, M=S*N, N=D, K=D)
//   out[s,i,j] = sum_d tensor1[s,i,d] * qt0[s,j,d] + bias    (batched GEMM-NT, M=N, N=N, K=D)

#define BM 128
#define BN 128
#define BK 16
#define TM 8
#define TN 8
#define NTHREADS 256

static const int S_ = 8;
static const int N_ = 2048;
static const int D_ = 256;

// Scratch for the intermediate qt0 (S*N*D fp32 = 16 MB). __device__ global: no alloc.
__device__ float g_qt0[8 * 2048 * 256];

// C[m][n] = sum_k A[m][k] * B[n][k]  (+ bias if add_bias)
// A: [M,K] row-major, B: [Nn,K] row-major, C: [M,Nn] row-major.
// All tile dims assumed to divide M, Nn, K exactly (true for this problem).
__global__ __launch_bounds__(NTHREADS, 2)
void gemm_nt_kernel(const float* __restrict__ A,
                    const float* __restrict__ B,
                    float* __restrict__ C,
                    int M, int Nn, int K,
                    long strideA, long strideB, long strideC,
                    const float* __restrict__ bias_ptr, int add_bias)
{
    const int b = blockIdx.z;
    A += (long)b * strideA;
    B += (long)b * strideB;
    C += (long)b * strideC;

    __shared__ float As[BK][BM];
    __shared__ float Bs[BK][BN];

    const int tid = threadIdx.x;        // 0..255
    const int tx  = tid % 16;           // n-tile position
    const int ty  = tid / 16;           // m-tile position
    const int m0  = blockIdx.y * BM;
    const int n0  = blockIdx.x * BN;

    // Loader mapping: 256 threads, each loads 2 float4 from A and 2 from B per k-step.
    // 128 rows x 16 cols = 2048 floats = 512 float4; thread t loads rows (t/4) and (t/4 + 64),
    // col group (t%4)*4.
    const int lr = tid >> 2;            // 0..63
    const int lc = (tid & 3) * 4;       // 0,4,8,12

    float acc[TM][TN];
    #pragma unroll
    for (int i = 0; i < TM; i++)
        #pragma unroll
        for (int j = 0; j < TN; j++)
            acc[i][j] = 0.0f;

    for (int k0 = 0; k0 < K; k0 += BK) {
        #pragma unroll
        for (int h = 0; h < 2; h++) {
            const int r = lr + h * 64;
            float4 va = *(const float4*)(A + (long)(m0 + r) * K + k0 + lc);
            As[lc + 0][r] = va.x;
            As[lc + 1][r] = va.y;
            As[lc + 2][r] = va.z;
            As[lc + 3][r] = va.w;
            float4 vb = *(const float4*)(B + (long)(n0 + r) * K + k0 + lc);
            Bs[lc + 0][r] = vb.x;
            Bs[lc + 1][r] = vb.y;
            Bs[lc + 2][r] = vb.z;
            Bs[lc + 3][r] = vb.w;
        }
        __syncthreads();

        #pragma unroll
        for (int k = 0; k < BK; k++) {
            float ra[TM], rb[TN];
            // vectorized shared reads (2x float4 each)
            float4 a0 = *(const float4*)&As[k][ty * TM + 0];
            float4 a1 = *(const float4*)&As[k][ty * TM + 4];
            ra[0] = a0.x; ra[1] = a0.y; ra[2] = a0.z; ra[3] = a0.w;
            ra[4] = a1.x; ra[5] = a1.y; ra[6] = a1.z; ra[7] = a1.w;
            float4 b0 = *(const float4*)&Bs[k][tx * TN + 0];
            float4 b1 = *(const float4*)&Bs[k][tx * TN + 4];
            rb[0] = b0.x; rb[1] = b0.y; rb[2] = b0.z; rb[3] = b0.w;
            rb[4] = b1.x; rb[5] = b1.y; rb[6] = b1.z; rb[7] = b1.w;

            #pragma unroll
            for (int i = 0; i < TM; i++)
                #pragma unroll
                for (int j = 0; j < TN; j++)
                    acc[i][j] = fmaf(ra[i], rb[j], acc[i][j]);
        }
        __syncthreads();
    }

    float bias = add_bias ? bias_ptr[0] : 0.0f;

    #pragma unroll
    for (int i = 0; i < TM; i++) {
        float* crow = C + (long)(m0 + ty * TM + i) * Nn + n0 + tx * TN;
        #pragma unroll
        for (int j = 0; j < TN; j += 4) {
            float4 v = make_float4(acc[i][j + 0] + bias,
                                   acc[i][j + 1] + bias,
                                   acc[i][j + 2] + bias,
                                   acc[i][j + 3] + bias);
            *(float4*)(crow + j) = v;
        }
    }
}

extern "C" void kernel_launch(void* const* d_in, const int* in_sizes, int n_in,
                              void* d_out, int out_size)
{
    const float* tensor0 = (const float*)d_in[0];  // [S, N, D]
    const float* tensor1 = (const float*)d_in[1];  // [S, N, D]
    const float* kernelw = (const float*)d_in[2];  // [D, D]
    const float* bias    = (const float*)d_in[3];  // [1]
    float* out = (float*)d_out;                    // [S, N, N]

    float* qt0 = nullptr;
    cudaGetSymbolAddress((void**)&qt0, g_qt0);

    // Step 1: qt0[j,d] = sum_e tensor0[j,e] * kernel[d,e]
    //         M = S*N = 16384, Nn = D = 256, K = D = 256, single batch.
    {
        dim3 grid(D_ / BN, (S_ * N_) / BM, 1);
        gemm_nt_kernel<<<grid, NTHREADS>>>(tensor0, kernelw, qt0,
                                           S_ * N_, D_, D_,
                                           0, 0, 0,
                                           nullptr, 0);
    }

    // Step 2: out[s,i,j] = sum_d tensor1[s,i,d] * qt0[s,j,d] + bias
    //         M = N = 2048, Nn = N = 2048, K = D = 256, batch = S.
    {
        dim3 grid(N_ / BN, N_ / BM, S_);
        gemm_nt_kernel<<<grid, NTHREADS>>>(tensor1, qt0, out,
                                           N_, N_, D_,
                                           (long)N_ * D_, (long)N_ * D_, (long)N_ * N_,
                                           bias, 1);
    }
}

// round 3
// speedup vs baseline: 2.0228x; 2.0228x over previous
#include <cuda_runtime.h>
#include <cuda_bf16.h>
#include <cstdint>

// Problem: S=8, N=2048, D=256
//   qt0[s,j,d] = sum_e tensor0[s,j,e] * kernel[d,e]       (NT GEMM, M=16384, N=256, K=256)
//   out[s,i,j] = sum_d tensor1[s,i,d] * qt0[s,j,d] + bias (batched NT, 2048x2048x256 x8)
//
// sm_103 base-ISA tensor path: mma.sync.m16n8k16 bf16 with 3-term split-fp32:
//   x = h + l  (h = truncate-to-bf16(x), l = bf16(x - h))
//   x*y ~= h_x*h_y + l_x*h_y + h_x*l_y        (rel err ~2^-17)

#define BM 128
#define BN 128
#define CK 32              // fp32 K per chunk
#define NTHREADS 256
#define ROWB 80            // smem row stride bytes (32 bf16 = 64B + 16B pad -> conflict-free ldmatrix)
#define TILEB (128 * ROWB) // one 128x32 bf16 tile

static const int S_ = 8;
static const int N_ = 2048;
static const int D_ = 256;

__device__ float g_qt0[8 * 2048 * 256];   // 16 MB scratch (no allocs allowed)

__device__ __forceinline__ uint32_t smem_u32(const void* p) {
    uint32_t a;
    asm("{ .reg .u64 t; cvta.to.shared.u64 t, %1; cvt.u32.u64 %0, t; }" : "=r"(a) : "l"(p));
    return a;
}
__device__ __forceinline__ void ldsm4(uint32_t* r, uint32_t addr) {
    asm volatile("ldmatrix.sync.aligned.m8n8.x4.shared.b16 {%0,%1,%2,%3}, [%4];"
                 : "=r"(r[0]), "=r"(r[1]), "=r"(r[2]), "=r"(r[3]) : "r"(addr));
}
__device__ __forceinline__ void mma16816(float* c, const uint32_t* a, uint32_t b0, uint32_t b1) {
    asm volatile("mma.sync.aligned.m16n8k16.row.col.f32.bf16.bf16.f32 "
                 "{%0,%1,%2,%3}, {%4,%5,%6,%7}, {%8,%9}, {%0,%1,%2,%3};"
                 : "+f"(c[0]), "+f"(c[1]), "+f"(c[2]), "+f"(c[3])
                 : "r"(a[0]), "r"(a[1]), "r"(a[2]), "r"(a[3]), "r"(b0), "r"(b1));
}
__device__ __forceinline__ uint32_t cvt_bf16x2(float hi, float lo) {
    uint32_t d;
    asm("cvt.rn.bf16x2.f32 %0, %1, %2;" : "=r"(d) : "f"(hi), "f"(lo));
    return d;
}

// Convert float4 -> h (2x bf16x2 via PRMT of high halves) and l (residual) and store.
__device__ __forceinline__ void split_sts(char* smem, int hOff, int lOff, float4 v) {
    uint32_t xb = __float_as_uint(v.x), yb = __float_as_uint(v.y);
    uint32_t zb = __float_as_uint(v.z), wb = __float_as_uint(v.w);
    uint32_t h01 = __byte_perm(xb, yb, 0x7632);
    uint32_t h23 = __byte_perm(zb, wb, 0x7632);
    float l0 = v.x - __uint_as_float(xb & 0xFFFF0000u);
    float l1 = v.y - __uint_as_float(yb & 0xFFFF0000u);
    float l2 = v.z - __uint_as_float(zb & 0xFFFF0000u);
    float l3 = v.w - __uint_as_float(wb & 0xFFFF0000u);
    uint32_t l01 = cvt_bf16x2(l1, l0);
    uint32_t l23 = cvt_bf16x2(l3, l2);
    *(uint2*)(smem + hOff) = make_uint2(h01, h23);
    *(uint2*)(smem + lOff) = make_uint2(l01, l23);
}

// C[b,m,n] = sum_k A[b,m,k] * B[b,n,k] (+ bias). K % 32 == 0, tiles exact.
__global__ __launch_bounds__(NTHREADS)
void gemm_mma_kernel(const float* __restrict__ A,
                     const float* __restrict__ B,
                     float* __restrict__ C,
                     int K, int ldA, int ldB, int ldC,
                     long strideA, long strideB, long strideC,
                     const float* __restrict__ bias_ptr)
{
    // dyn smem: per buffer {Ah, Al, Bh, Bl} tiles of 128x32 bf16 (ROWB-stride), x2 buffers
    extern __shared__ __align__(16) char smem[];
    const uint32_t sbase = smem_u32(smem);

    const int tid  = threadIdx.x;
    const int lane = tid & 31;
    const int wid  = tid >> 5;
    const int wm   = wid & 3;        // 4 warps along M -> 32 rows each
    const int wn   = wid >> 2;       // 2 warps along N -> 64 cols each
    const int m0   = blockIdx.y * BM;
    const int n0   = blockIdx.x * BN;
    const int b    = blockIdx.z;

    const float* Ab = A + (long)b * strideA + (long)m0 * ldA;
    const float* Bb = B + (long)b * strideB + (long)n0 * ldB;
    float* Cb       = C + (long)b * strideC;

    // loader mapping: thread -> (row, col4) covering 128x32 fp32 in 4 steps
    const int lrow = tid >> 3;            // 0..31 (+32*i)
    const int lcol = (tid & 7) * 4;       // fp32 col: 0,4,...,28

    float acc[2][8][4];
    #pragma unroll
    for (int mt = 0; mt < 2; mt++)
        #pragma unroll
        for (int nt = 0; nt < 8; nt++)
            #pragma unroll
            for (int j = 0; j < 4; j++)
                acc[mt][nt][j] = 0.0f;

    const int nchunk = K / CK;
    float4 ra[4], rb[4];

    // ldmatrix lane addressing (within a 16-row x 16-col bf16 block)
    const uint32_t lmOff = (uint32_t)((lane & 15) * ROWB + (lane >> 4) * 16);
    const uint32_t aWarp = (uint32_t)(wm * 32 * ROWB) + lmOff;
    const uint32_t bWarp = (uint32_t)(wn * 64 * ROWB) + lmOff;

    // ---- preload chunk 0 ----
    #pragma unroll
    for (int i = 0; i < 4; i++) {
        ra[i] = *(const float4*)(Ab + (long)(lrow + 32 * i) * ldA + lcol);
        rb[i] = *(const float4*)(Bb + (long)(lrow + 32 * i) * ldB + lcol);
    }
    {
        const int base = 0;  // buffer 0
        #pragma unroll
        for (int i = 0; i < 4; i++) {
            int ro = (lrow + 32 * i) * ROWB + lcol * 2;
            split_sts(smem, base + ro,             base + TILEB + ro,     ra[i]);
            split_sts(smem, base + 2 * TILEB + ro, base + 3 * TILEB + ro, rb[i]);
        }
    }
    __syncthreads();

    for (int c = 0; c < nchunk; c++) {
        const uint32_t bufB = (uint32_t)((c & 1) * 4 * TILEB);

        // prefetch next chunk into registers
        if (c + 1 < nchunk) {
            const int k0 = (c + 1) * CK;
            #pragma unroll
            for (int i = 0; i < 4; i++) {
                ra[i] = *(const float4*)(Ab + (long)(lrow + 32 * i) * ldA + k0 + lcol);
                rb[i] = *(const float4*)(Bb + (long)(lrow + 32 * i) * ldB + k0 + lcol);
            }
        }

        // ---- MMA on current buffer ----
        const uint32_t aH0 = sbase + bufB + aWarp;
        const uint32_t aL0 = aH0 + TILEB;
        const uint32_t bH0 = sbase + bufB + 2 * TILEB + bWarp;
        const uint32_t bL0 = bH0 + TILEB;

        #pragma unroll
        for (int ks = 0; ks < 2; ks++) {
            const uint32_t ko = ks * 32;   // 16 bf16 = 32 bytes
            uint32_t aH[8], aL[8], bH[16], bL[16];
            ldsm4(aH + 0, aH0 + ko);
            ldsm4(aH + 4, aH0 + 16 * ROWB + ko);
            ldsm4(aL + 0, aL0 + ko);
            ldsm4(aL + 4, aL0 + 16 * ROWB + ko);
            #pragma unroll
            for (int p = 0; p < 4; p++) {
                ldsm4(bH + 4 * p, bH0 + p * 16 * ROWB + ko);
                ldsm4(bL + 4 * p, bL0 + p * 16 * ROWB + ko);
            }
            #pragma unroll
            for (int mt = 0; mt < 2; mt++) {
                #pragma unroll
                for (int nt = 0; nt < 8; nt++) {
                    const int p = nt >> 1, o = nt & 1;
                    const uint32_t hb0 = bH[4 * p + o], hb1 = bH[4 * p + 2 + o];
                    const uint32_t lb0 = bL[4 * p + o], lb1 = bL[4 * p + 2 + o];
                    mma16816(acc[mt][nt], aH + 4 * mt, hb0, hb1);  // h*h
                    mma16816(acc[mt][nt], aL + 4 * mt, hb0, hb1);  // l*h
                    mma16816(acc[mt][nt], aH + 4 * mt, lb0, lb1);  // h*l
                }
            }
        }
        __syncthreads();

        // store prefetched chunk into the other buffer
        if (c + 1 < nchunk) {
            const int base = ((c + 1) & 1) * 4 * TILEB;
            #pragma unroll
            for (int i = 0; i < 4; i++) {
                int ro = (lrow + 32 * i) * ROWB + lcol * 2;
                split_sts(smem, base + ro,             base + TILEB + ro,     ra[i]);
                split_sts(smem, base + 2 * TILEB + ro, base + 3 * TILEB + ro, rb[i]);
            }
            __syncthreads();
        }
    }

    // ---- epilogue ----
    const float bv = bias_ptr ? bias_ptr[0] : 0.0f;
    const int rbase = m0 + wm * 32 + (lane >> 2);
    const int cbase = n0 + wn * 64 + (lane & 3) * 2;
    #pragma unroll
    for (int mt = 0; mt < 2; mt++) {
        #pragma unroll
        for (int nt = 0; nt < 8; nt++) {
            const int r = rbase + mt * 16;
            const int cc = cbase + nt * 8;
            float2 v0 = make_float2(acc[mt][nt][0] + bv, acc[mt][nt][1] + bv);
            float2 v1 = make_float2(acc[mt][nt][2] + bv, acc[mt][nt][3] + bv);
            *(float2*)(Cb + (long)r * ldC + cc)       = v0;
            *(float2*)(Cb + (long)(r + 8) * ldC + cc) = v1;
        }
    }
}

#define SMEM_BYTES (8 * TILEB)   // 81920

extern "C" void kernel_launch(void* const* d_in, const int* in_sizes, int n_in,
                              void* d_out, int out_size)
{
    const float* tensor0 = (const float*)d_in[0];  // [S, N, D]
    const float* tensor1 = (const float*)d_in[1];  // [S, N, D]
    const float* kernelw = (const float*)d_in[2];  // [D, D]
    const float* bias    = (const float*)d_in[3];  // [1]
    float* out = (float*)d_out;                    // [S, N, N]

    float* qt0 = nullptr;
    cudaGetSymbolAddress((void**)&qt0, g_qt0);

    cudaFuncSetAttribute(gemm_mma_kernel,
                         cudaFuncAttributeMaxDynamicSharedMemorySize, SMEM_BYTES);

    // GEMM1: qt0[j,d] = sum_e tensor0[j,e] * kernel[d,e]; M=16384, N=256, K=256
    {
        dim3 grid(D_ / BN, (S_ * N_) / BM, 1);
        gemm_mma_kernel<<<grid, NTHREADS, SMEM_BYTES>>>(
            tensor0, kernelw, qt0, D_, D_, D_, D_, 0, 0, 0, nullptr);
    }
    // GEMM2: out[s,i,j] = sum_d tensor1[s,i,d] * qt0[s,j,d] + bias; 2048x2048x256 x8
    {
        dim3 grid(N_ / BN, N_ / BM, S_);
        gemm_mma_kernel<<<grid, NTHREADS, SMEM_BYTES>>>(
            tensor1, qt0, out, D_, D_, D_, N_,
            (long)N_ * D_, (long)N_ * D_, (long)N_ * N_, bias);
    }
}

// round 4
// speedup vs baseline: 2.1761x; 1.0758x over previous
#include <cuda_runtime.h>
#include <cuda_bf16.h>
#include <cstdint>

// Problem: S=8, N=2048, D=256
//   qt0[s,j,d] = sum_e tensor0[s,j,e] * kernel[d,e]       (NT GEMM, M=16384, N=256, K=256)
//   out[s,i,j] = sum_d tensor1[s,i,d] * qt0[s,j,d] + bias (batched NT, 2048x2048x256 x8)
//
// sm_103 base-ISA tensor path: mma.sync.m16n8k16 bf16 with 3-term split-fp32:
//   x = h + l  (h = truncate-to-bf16(x), l = bf16(x - h))
//   x*y ~= h_x*h_y + l_x*h_y + h_x*l_y        (rel err ~2^-17)

#define BM 128
#define BN 128
#define CK 32              // fp32 K per chunk
#define NTHREADS 512
#define ROWB 80            // smem row stride bytes: conflict-free ldmatrix
#define TILEB (128 * ROWB) // one 128x32 bf16 tile (10 KB)

static const int S_ = 8;
static const int N_ = 2048;
static const int D_ = 256;

__device__ float g_qt0[8 * 2048 * 256];   // 16 MB scratch (no allocs allowed)

__device__ __forceinline__ uint32_t smem_u32(const void* p) {
    uint32_t a;
    asm("{ .reg .u64 t; cvta.to.shared.u64 t, %1; cvt.u32.u64 %0, t; }" : "=r"(a) : "l"(p));
    return a;
}
__device__ __forceinline__ void ldsm4(uint32_t* r, uint32_t addr) {
    asm volatile("ldmatrix.sync.aligned.m8n8.x4.shared.b16 {%0,%1,%2,%3}, [%4];"
                 : "=r"(r[0]), "=r"(r[1]), "=r"(r[2]), "=r"(r[3]) : "r"(addr));
}
__device__ __forceinline__ void mma16816(float* c, const uint32_t* a, uint32_t b0, uint32_t b1) {
    asm volatile("mma.sync.aligned.m16n8k16.row.col.f32.bf16.bf16.f32 "
                 "{%0,%1,%2,%3}, {%4,%5,%6,%7}, {%8,%9}, {%0,%1,%2,%3};"
                 : "+f"(c[0]), "+f"(c[1]), "+f"(c[2]), "+f"(c[3])
                 : "r"(a[0]), "r"(a[1]), "r"(a[2]), "r"(a[3]), "r"(b0), "r"(b1));
}
__device__ __forceinline__ uint32_t cvt_bf16x2(float hi, float lo) {
    uint32_t d;
    asm("cvt.rn.bf16x2.f32 %0, %1, %2;" : "=r"(d) : "f"(hi), "f"(lo));
    return d;
}

// float4 -> h (2x bf16x2 via PRMT of high halves) + l (residual), store 8B each.
__device__ __forceinline__ void split_sts(char* smem, int hOff, int lOff, float4 v) {
    uint32_t xb = __float_as_uint(v.x), yb = __float_as_uint(v.y);
    uint32_t zb = __float_as_uint(v.z), wb = __float_as_uint(v.w);
    uint32_t h01 = __byte_perm(xb, yb, 0x7632);
    uint32_t h23 = __byte_perm(zb, wb, 0x7632);
    float l0 = v.x - __uint_as_float(xb & 0xFFFF0000u);
    float l1 = v.y - __uint_as_float(yb & 0xFFFF0000u);
    float l2 = v.z - __uint_as_float(zb & 0xFFFF0000u);
    float l3 = v.w - __uint_as_float(wb & 0xFFFF0000u);
    uint32_t l01 = cvt_bf16x2(l1, l0);
    uint32_t l23 = cvt_bf16x2(l3, l2);
    *(uint2*)(smem + hOff) = make_uint2(h01, h23);
    *(uint2*)(smem + lOff) = make_uint2(l01, l23);
}

// C[b,m,n] = sum_k A[b,m,k] * B[b,n,k] (+ bias). K % 32 == 0, tiles exact.
__global__ __launch_bounds__(NTHREADS, 1)
void gemm_mma_kernel(const float* __restrict__ A,
                     const float* __restrict__ B,
                     float* __restrict__ C,
                     int K, int ldA, int ldB, int ldC,
                     long strideA, long strideB, long strideC,
                     const float* __restrict__ bias_ptr)
{
    // dyn smem: per buffer {Ah, Al, Bh, Bl} 128x32 bf16 tiles (ROWB stride), x2 buffers
    extern __shared__ __align__(16) char smem[];
    const uint32_t sbase = smem_u32(smem);

    const int tid  = threadIdx.x;
    const int lane = tid & 31;
    const int wid  = tid >> 5;        // 0..15
    const int wm   = wid & 3;         // 4 warps along M -> 32 rows each
    const int wn   = wid >> 2;        // 4 warps along N -> 32 cols each
    const int m0   = blockIdx.y * BM;
    const int n0   = blockIdx.x * BN;
    const int b    = blockIdx.z;

    const float* Ab = A + (long)b * strideA + (long)m0 * ldA;
    const float* Bb = B + (long)b * strideB + (long)n0 * ldB;
    float* Cb       = C + (long)b * strideC;

    // loader: 512 threads cover 128 rows x 8 col4-groups twice (i=0,1)
    const int lrow = tid >> 3;            // 0..63 (+64 for i=1)
    const int lcol = (tid & 7) * 4;       // fp32 col 0..28

    float acc[2][4][4];
    #pragma unroll
    for (int mt = 0; mt < 2; mt++)
        #pragma unroll
        for (int nt = 0; nt < 4; nt++)
            #pragma unroll
            for (int j = 0; j < 4; j++)
                acc[mt][nt][j] = 0.0f;

    const int nchunk = K / CK;
    float4 ra[2], rb[2];

    // ldmatrix lane addressing
    const uint32_t lmOff = (uint32_t)((lane & 15) * ROWB + (lane >> 4) * 16);
    const uint32_t aWarp = (uint32_t)(wm * 32 * ROWB) + lmOff;
    const uint32_t bWarp = (uint32_t)(wn * 32 * ROWB) + lmOff;

    // ---- preload + store chunk 0 ----
    #pragma unroll
    for (int i = 0; i < 2; i++) {
        ra[i] = *(const float4*)(Ab + (long)(lrow + 64 * i) * ldA + lcol);
        rb[i] = *(const float4*)(Bb + (long)(lrow + 64 * i) * ldB + lcol);
    }
    #pragma unroll
    for (int i = 0; i < 2; i++) {
        int ro = (lrow + 64 * i) * ROWB + lcol * 2;
        split_sts(smem, ro,             TILEB + ro,     ra[i]);
        split_sts(smem, 2 * TILEB + ro, 3 * TILEB + ro, rb[i]);
    }
    __syncthreads();

    for (int c = 0; c < nchunk; c++) {
        const uint32_t bufB = (uint32_t)((c & 1) * 4 * TILEB);
        const int nbase = ((c + 1) & 1) * 4 * TILEB;
        const bool more = (c + 1 < nchunk);

        // prefetch next chunk into registers
        if (more) {
            const int k0 = (c + 1) * CK;
            #pragma unroll
            for (int i = 0; i < 2; i++) {
                ra[i] = *(const float4*)(Ab + (long)(lrow + 64 * i) * ldA + k0 + lcol);
                rb[i] = *(const float4*)(Bb + (long)(lrow + 64 * i) * ldB + k0 + lcol);
            }
        }

        const uint32_t aH0 = sbase + bufB + aWarp;
        const uint32_t aL0 = aH0 + TILEB;
        const uint32_t bH0 = sbase + bufB + 2 * TILEB + bWarp;
        const uint32_t bL0 = bH0 + TILEB;

        #pragma unroll
        for (int ks = 0; ks < 2; ks++) {
            const uint32_t ko = ks * 32;   // 16 bf16 = 32B
            uint32_t aH[8], aL[8], bH[8], bL[8];
            ldsm4(aH + 0, aH0 + ko);
            ldsm4(aH + 4, aH0 + 16 * ROWB + ko);
            ldsm4(aL + 0, aL0 + ko);
            ldsm4(aL + 4, aL0 + 16 * ROWB + ko);
            ldsm4(bH + 0, bH0 + ko);
            ldsm4(bH + 4, bH0 + 16 * ROWB + ko);
            ldsm4(bL + 0, bL0 + ko);
            ldsm4(bL + 4, bL0 + 16 * ROWB + ko);

            // interleave next-chunk conversion+STS with the MMA burst
            if (more) {
                int ro = (lrow + 64 * ks) * ROWB + lcol * 2;
                split_sts(smem, nbase + ro,             nbase + TILEB + ro,     ra[ks]);
                split_sts(smem, nbase + 2 * TILEB + ro, nbase + 3 * TILEB + ro, rb[ks]);
            }

            #pragma unroll
            for (int mt = 0; mt < 2; mt++) {
                #pragma unroll
                for (int nt = 0; nt < 4; nt++) {
                    const int p = nt >> 1, o = nt & 1;
                    const uint32_t hb0 = bH[4 * p + o], hb1 = bH[4 * p + 2 + o];
                    const uint32_t lb0 = bL[4 * p + o], lb1 = bL[4 * p + 2 + o];
                    mma16816(acc[mt][nt], aH + 4 * mt, hb0, hb1);  // h*h
                    mma16816(acc[mt][nt], aL + 4 * mt, hb0, hb1);  // l*h
                    mma16816(acc[mt][nt], aH + 4 * mt, lb0, lb1);  // h*l
                }
            }
        }
        __syncthreads();   // next buffer fully written; current buffer free
    }

    // ---- epilogue ----
    const float bv = bias_ptr ? bias_ptr[0] : 0.0f;
    const int rbase = m0 + wm * 32 + (lane >> 2);
    const int cbase = n0 + wn * 32 + (lane & 3) * 2;
    #pragma unroll
    for (int mt = 0; mt < 2; mt++) {
        #pragma unroll
        for (int nt = 0; nt < 4; nt++) {
            const int r = rbase + mt * 16;
            const int cc = cbase + nt * 8;
            float2 v0 = make_float2(acc[mt][nt][0] + bv, acc[mt][nt][1] + bv);
            float2 v1 = make_float2(acc[mt][nt][2] + bv, acc[mt][nt][3] + bv);
            *(float2*)(Cb + (long)r * ldC + cc)       = v0;
            *(float2*)(Cb + (long)(r + 8) * ldC + cc) = v1;
        }
    }
}

#define SMEM_BYTES (8 * TILEB)   // 81920

extern "C" void kernel_launch(void* const* d_in, const int* in_sizes, int n_in,
                              void* d_out, int out_size)
{
    const float* tensor0 = (const float*)d_in[0];  // [S, N, D]
    const float* tensor1 = (const float*)d_in[1];  // [S, N, D]
    const float* kernelw = (const float*)d_in[2];  // [D, D]
    const float* bias    = (const float*)d_in[3];  // [1]
    float* out = (float*)d_out;                    // [S, N, N]

    float* qt0 = nullptr;
    cudaGetSymbolAddress((void**)&qt0, g_qt0);

    cudaFuncSetAttribute(gemm_mma_kernel,
                         cudaFuncAttributeMaxDynamicSharedMemorySize, SMEM_BYTES);

    // GEMM1: qt0[j,d] = sum_e tensor0[j,e] * kernel[d,e]; M=16384, N=256, K=256
    {
        dim3 grid(D_ / BN, (S_ * N_) / BM, 1);
        gemm_mma_kernel<<<grid, NTHREADS, SMEM_BYTES>>>(
            tensor0, kernelw, qt0, D_, D_, D_, D_, 0, 0, 0, nullptr);
    }
    // GEMM2: out[s,i,j] = sum_d tensor1[s,i,d] * qt0[s,j,d] + bias; 2048x2048x256 x8
    {
        dim3 grid(N_ / BN, N_ / BM, S_);
        gemm_mma_kernel<<<grid, NTHREADS, SMEM_BYTES>>>(
            tensor1, qt0, out, D_, D_, D_, N_,
            (long)N_ * D_, (long)N_ * D_, (long)N_ * N_, bias);
    }
}